// round 2
// baseline (speedup 1.0000x reference)
#include <cuda_runtime.h>
#include <math.h>

#define NEDGE 131072

// Level sizes: n (real), ld (padded to mult of 128)
// L0: 4096/4096  L1: 3277/3328  L2: 2622/2688  L3: 2098/2176

__device__ float g_A0[4096*4096];
__device__ float g_A1[3328*3328];
__device__ float g_A2[2688*2688];
__device__ float g_A3[2176*2176];
__device__ float g_Mr[3328*4096];
__device__ float g_Mc[3328*4096];
__device__ float g_Xs0[4096*64];
__device__ float g_Xs1[4096*64];
__device__ float g_Xs2[4096*64];
__device__ float g_Xa[4096*64];
__device__ float g_Xb[4096*64];
__device__ float g_Xup[4096*64];
__device__ float g_XW[4096*64];
__device__ float g_Z[4096*64];
__device__ float g_Y[4096*64];
__device__ float g_Part[32*4096];
__device__ float g_Dis[4096];
__device__ float g_Fill[4096];
__device__ float g_Score[4096];
__device__ float g_Sval[4096];
__device__ int   g_Perm0[4096];
__device__ int   g_Perm1[4096];
__device__ int   g_Perm2[4096];

// ---------------- basic kernels ----------------

__global__ void k_zero(float* p, int n) {
    int i = blockIdx.x * blockDim.x + threadIdx.x;
    if (i < n) p[i] = 0.f;
}

__global__ void k_edges(const int* __restrict__ ei, float* __restrict__ A) {
    int e = blockIdx.x * blockDim.x + threadIdx.x;
    if (e < NEDGE) {
        int s = ei[e], d = ei[NEDGE + e];
        if (s != d) atomicAdd(&A[(size_t)s * 4096 + d], 1.f);
    }
}

__global__ void k_eye(float* A) {
    int i = blockIdx.x * blockDim.x + threadIdx.x;
    if (i < 4096) A[(size_t)i * 4096 + i] += 1.f;
}

// xW: one block per row. XW always stride 64; pad cols [cout,64) zeroed.
__global__ void k_xw(const float* __restrict__ X, const float* __restrict__ W,
                     float* __restrict__ XW, int cin, int cout) {
    __shared__ float sx[64];
    int r = blockIdx.x;
    int f = threadIdx.x;
    for (int k = f; k < cin; k += 64) sx[k] = X[(size_t)r * cin + k];
    __syncthreads();
    float acc = 0.f;
    if (f < cout) {
        for (int k = 0; k < cin; k++) acc += sx[k] * W[k * cout + f];
    }
    XW[(size_t)r * 64 + f] = (f < cout) ? acc : 0.f;
}

// deterministic 2-pass column sum: 32 row-chunks
__global__ void k_colsum(const float* __restrict__ A, float* __restrict__ part,
                         int n, int ld) {
    int c = blockIdx.x * blockDim.x + threadIdx.x;
    int ch = blockIdx.y;
    if (c >= ld) return;
    int rpc = (n + 31) >> 5;
    int r0 = ch * rpc, r1 = min(r0 + rpc, n);
    float s = 0.f;
    for (int r = r0; r < r1; r++) s += A[(size_t)r * ld + c];
    part[ch * 4096 + c] = s;
}

__global__ void k_dis(const float* __restrict__ A, const float* __restrict__ part,
                      float* __restrict__ dis, float* __restrict__ fill, int n, int ld) {
    int c = blockIdx.x * blockDim.x + threadIdx.x;
    if (c >= ld) return;
    if (c >= n) { dis[c] = 0.f; fill[c] = 0.f; return; }
    float s = 0.f;
#pragma unroll
    for (int ch = 0; ch < 32; ch++) s += part[ch * 4096 + c];
    float F = (A[(size_t)c * ld + c] == 0.f) ? 2.f : 0.f;
    float d = s + F;
    dis[c]  = (d > 0.f) ? (1.f / sqrtf(d)) : 0.f;
    fill[c] = F;
}

// Z[r,f] = dis[r]*XW[r,f] for r<n, 0 for pad rows
__global__ void k_scale(const float* __restrict__ XW, const float* __restrict__ dis,
                        float* __restrict__ Z, int n, int ld) {
    int idx = blockIdx.x * blockDim.x + threadIdx.x;
    if (idx >= ld * 64) return;
    int r = idx >> 6;
    Z[idx] = (r < n) ? dis[r] * XW[idx] : 0.f;
}

// Y = A^T @ Z  (A row-major [k][m], ld x ld; Z ld x 64). Tile 64m x 64f x 16k.
__global__ void __launch_bounds__(256) k_atz(const float* __restrict__ A,
                                             const float* __restrict__ Z,
                                             float* __restrict__ Y, int ld) {
    __shared__ float As[16][64];
    __shared__ float Zs[16][64];
    int mb = blockIdx.x * 64;
    int tid = threadIdx.x;
    int tm = (tid & 15) * 4;
    int tf = (tid >> 4) * 4;
    float acc[4][4] = {};
    for (int k0 = 0; k0 < ld; k0 += 16) {
        for (int idx = tid; idx < 16 * 64; idx += 256) {
            int kk = idx >> 6, mm = idx & 63;
            As[kk][mm] = A[(size_t)(k0 + kk) * ld + mb + mm];
            Zs[kk][mm] = Z[(size_t)(k0 + kk) * 64 + mm];
        }
        __syncthreads();
#pragma unroll
        for (int kk = 0; kk < 16; kk++) {
            float a[4], b[4];
#pragma unroll
            for (int i = 0; i < 4; i++) a[i] = As[kk][tm + i];
#pragma unroll
            for (int j = 0; j < 4; j++) b[j] = Zs[kk][tf + j];
#pragma unroll
            for (int i = 0; i < 4; i++)
#pragma unroll
                for (int j = 0; j < 4; j++) acc[i][j] += a[i] * b[j];
        }
        __syncthreads();
    }
#pragma unroll
    for (int i = 0; i < 4; i++)
#pragma unroll
        for (int j = 0; j < 4; j++)
            Y[(size_t)(mb + tm + i) * 64 + tf + j] = acc[i][j];
}

__global__ void k_fin(const float* __restrict__ Y, const float* __restrict__ Z,
                      const float* __restrict__ dis, const float* __restrict__ fill,
                      const float* __restrict__ bias, float* __restrict__ out,
                      int n, int cout, int dorelu) {
    int idx = blockIdx.x * blockDim.x + threadIdx.x;
    if (idx >= n * cout) return;
    int c = idx / cout, f = idx - c * cout;
    float v = dis[c] * (Y[(size_t)c * 64 + f] + fill[c] * Z[(size_t)c * 64 + f]) + bias[f];
    if (dorelu) v = fmaxf(v, 0.f);
    out[idx] = v;
}

__global__ void k_score(const float* __restrict__ X, const float* __restrict__ p,
                        float* __restrict__ score, int n) {
    int r = blockIdx.x * blockDim.x + threadIdx.x;
    if (r >= n) return;
    float dot = 0.f, pn = 0.f;
#pragma unroll
    for (int k = 0; k < 64; k++) { dot += X[(size_t)r * 64 + k] * p[k]; pn += p[k] * p[k]; }
    score[r] = tanhf(dot / sqrtf(pn));
}

// full bitonic sort of 4096 (score desc, tie: smaller index first)
__global__ void k_sort(const float* __restrict__ score, int n, int k,
                       int* __restrict__ perm, float* __restrict__ sval) {
    __shared__ float s[4096];
    __shared__ int id[4096];
    int tid = threadIdx.x;
    for (int i = tid; i < 4096; i += 1024) { s[i] = (i < n) ? score[i] : -INFINITY; id[i] = i; }
    __syncthreads();
    for (int sz = 2; sz <= 4096; sz <<= 1) {
        for (int j = sz >> 1; j > 0; j >>= 1) {
            for (int i = tid; i < 4096; i += 1024) {
                int ixj = i ^ j;
                if (ixj > i) {
                    float si = s[i], sj = s[ixj];
                    int ii = id[i], ij = id[ixj];
                    bool before = (si > sj) || (si == sj && ii < ij);
                    bool up = ((i & sz) == 0);
                    if (up ? !before : before) {
                        s[i] = sj; s[ixj] = si; id[i] = ij; id[ixj] = ii;
                    }
                }
            }
            __syncthreads();
        }
    }
    for (int a = tid; a < k; a += 1024) { perm[a] = id[a]; sval[a] = s[a]; }
}

__global__ void k_gatherx(const float* __restrict__ X, const int* __restrict__ perm,
                          const float* __restrict__ sval, float* __restrict__ Xo, int k) {
    int idx = blockIdx.x * blockDim.x + threadIdx.x;
    if (idx >= k * 64) return;
    int a = idx >> 6, f = idx & 63;
    Xo[idx] = X[(size_t)perm[a] * 64 + f] * sval[a];
}

// Mr[a,k] = M[perm[a],k]  where M = A with diag replaced by 1; pads zero.
__global__ void k_gMr(const float* __restrict__ A, const int* __restrict__ perm,
                      float* __restrict__ Mr, int kreal, int Kreal, int Kpad,
                      int ldA, int total) {
    int idx = blockIdx.x * blockDim.x + threadIdx.x;
    if (idx >= total) return;
    int a = idx / Kpad, k = idx - a * Kpad;
    float v = 0.f;
    if (a < kreal && k < Kreal) {
        int p = perm[a];
        v = (p == k) ? 1.f : A[(size_t)p * ldA + k];
    }
    Mr[idx] = v;
}

// Mc[k,b] = M[k,perm[b]]
__global__ void k_gMc(const float* __restrict__ A, const int* __restrict__ perm,
                      float* __restrict__ Mc, int kreal, int Kreal, int Npad,
                      int ldA, int total) {
    int idx = blockIdx.x * blockDim.x + threadIdx.x;
    if (idx >= total) return;
    int k = idx / Npad, b = idx - k * Npad;
    float v = 0.f;
    if (k < Kreal && b < kreal) {
        int p = perm[b];
        v = (k == p) ? 1.f : A[(size_t)k * ldA + p];
    }
    Mc[idx] = v;
}

// C[MxN] = A[MxK] @ B[KxN], all row-major, dims multiples of (128,128,8)
__global__ void __launch_bounds__(256) k_sgemm(const float* __restrict__ A,
                                               const float* __restrict__ B,
                                               float* __restrict__ C,
                                               int M, int N, int K) {
    __shared__ float As[8][128];
    __shared__ float Bs[8][128];
    int tid = threadIdx.x;
    int bm = blockIdx.y * 128, bn = blockIdx.x * 128;
    int tx = tid & 15, ty = tid >> 4;
    int arow = tid >> 1, acol = (tid & 1) * 4;
    int brow = tid >> 5, bcol = (tid & 31) * 4;
    float acc[8][8] = {};
    const float* Ap = A + (size_t)(bm + arow) * K + acol;
    const float* Bp = B + (size_t)brow * N + bn + bcol;
    for (int k0 = 0; k0 < K; k0 += 8) {
        float4 av = *(const float4*)(Ap + k0);
        float4 bv = *(const float4*)(Bp + (size_t)k0 * N);
        As[acol + 0][arow] = av.x;
        As[acol + 1][arow] = av.y;
        As[acol + 2][arow] = av.z;
        As[acol + 3][arow] = av.w;
        *(float4*)&Bs[brow][bcol] = bv;
        __syncthreads();
#pragma unroll
        for (int kk = 0; kk < 8; kk++) {
            float ar[8], br[8];
#pragma unroll
            for (int i = 0; i < 8; i++) ar[i] = As[kk][ty * 8 + i];
#pragma unroll
            for (int j = 0; j < 8; j++) br[j] = Bs[kk][tx * 8 + j];
#pragma unroll
            for (int i = 0; i < 8; i++)
#pragma unroll
                for (int j = 0; j < 8; j++) acc[i][j] += ar[i] * br[j];
        }
        __syncthreads();
    }
#pragma unroll
    for (int i = 0; i < 8; i++)
#pragma unroll
        for (int j = 0; j < 8; j++)
            C[(size_t)(bm + ty * 8 + i) * N + bn + tx * 8 + j] = acc[i][j];
}

__global__ void k_zdiag(float* A, int ld, int k) {
    int a = blockIdx.x * blockDim.x + threadIdx.x;
    if (a < k) A[(size_t)a * ld + a] = 0.f;
}

__global__ void k_copy(const float* __restrict__ src, float* __restrict__ dst, int n) {
    int i = blockIdx.x * blockDim.x + threadIdx.x;
    if (i < n) dst[i] = src[i];
}

__global__ void k_scatadd(const float* __restrict__ Xc, const int* __restrict__ perm,
                          float* __restrict__ Xup, int k) {
    int idx = blockIdx.x * blockDim.x + threadIdx.x;
    if (idx >= k * 64) return;
    int a = idx >> 6, f = idx & 63;
    Xup[(size_t)perm[a] * 64 + f] += Xc[idx];
}

// ---------------- host orchestration ----------------

static void run_gcn(const float* A, int n, int ld, const float* X, int cin,
                    const float* W, const float* bias, int cout, bool dorelu,
                    float* Xout, float* pXW, float* pZ, float* pY,
                    float* pDis, float* pFill, float* pPart) {
    k_xw<<<n, 64>>>(X, W, pXW, cin, cout);
    dim3 g1((ld + 255) / 256, 32);
    k_colsum<<<g1, 256>>>(A, pPart, n, ld);
    k_dis<<<(ld + 255) / 256, 256>>>(A, pPart, pDis, pFill, n, ld);
    k_scale<<<(ld * 64 + 255) / 256, 256>>>(pXW, pDis, pZ, n, ld);
    k_atz<<<ld / 64, 256>>>(A, pZ, pY, ld);
    k_fin<<<(n * cout + 255) / 256, 256>>>(pY, pZ, pDis, pFill, bias, Xout, n, cout,
                                           dorelu ? 1 : 0);
}

extern "C" void kernel_launch(void* const* d_in, const int* in_sizes, int n_in,
                              void* d_out, int out_size) {
    const float* x  = (const float*)d_in[0];
    const int*   ei = (const int*)d_in[1];
    const float* W0 = (const float*)d_in[2];  const float* b0 = (const float*)d_in[3];
    const float* W1 = (const float*)d_in[4];  const float* b1 = (const float*)d_in[5];
    const float* W2 = (const float*)d_in[6];  const float* b2 = (const float*)d_in[7];
    const float* W3 = (const float*)d_in[8];  const float* b3 = (const float*)d_in[9];
    const float* p1 = (const float*)d_in[10];
    const float* p2 = (const float*)d_in[11];
    const float* p3 = (const float*)d_in[12];
    const float* U0 = (const float*)d_in[13]; const float* c0 = (const float*)d_in[14];
    const float* U1 = (const float*)d_in[15]; const float* c1 = (const float*)d_in[16];
    const float* U2 = (const float*)d_in[17]; const float* c2 = (const float*)d_in[18];

    void* vp;
    float *A0p, *A1p, *A2p, *A3p, *Mrp, *Mcp;
    float *Xs0p, *Xs1p, *Xs2p, *Xap, *Xbp, *Xupp, *XWp, *Zp, *Yp, *Partp;
    float *Disp, *Fillp, *Scorep, *Svalp;
    int *P0p, *P1p, *P2p;
    cudaGetSymbolAddress(&vp, g_A0);  A0p  = (float*)vp;
    cudaGetSymbolAddress(&vp, g_A1);  A1p  = (float*)vp;
    cudaGetSymbolAddress(&vp, g_A2);  A2p  = (float*)vp;
    cudaGetSymbolAddress(&vp, g_A3);  A3p  = (float*)vp;
    cudaGetSymbolAddress(&vp, g_Mr);  Mrp  = (float*)vp;
    cudaGetSymbolAddress(&vp, g_Mc);  Mcp  = (float*)vp;
    cudaGetSymbolAddress(&vp, g_Xs0); Xs0p = (float*)vp;
    cudaGetSymbolAddress(&vp, g_Xs1); Xs1p = (float*)vp;
    cudaGetSymbolAddress(&vp, g_Xs2); Xs2p = (float*)vp;
    cudaGetSymbolAddress(&vp, g_Xa);  Xap  = (float*)vp;
    cudaGetSymbolAddress(&vp, g_Xb);  Xbp  = (float*)vp;
    cudaGetSymbolAddress(&vp, g_Xup); Xupp = (float*)vp;
    cudaGetSymbolAddress(&vp, g_XW);  XWp  = (float*)vp;
    cudaGetSymbolAddress(&vp, g_Z);   Zp   = (float*)vp;
    cudaGetSymbolAddress(&vp, g_Y);   Yp   = (float*)vp;
    cudaGetSymbolAddress(&vp, g_Part); Partp = (float*)vp;
    cudaGetSymbolAddress(&vp, g_Dis);  Disp  = (float*)vp;
    cudaGetSymbolAddress(&vp, g_Fill); Fillp = (float*)vp;
    cudaGetSymbolAddress(&vp, g_Score); Scorep = (float*)vp;
    cudaGetSymbolAddress(&vp, g_Sval);  Svalp  = (float*)vp;
    cudaGetSymbolAddress(&vp, g_Perm0); P0p = (int*)vp;
    cudaGetSymbolAddress(&vp, g_Perm1); P1p = (int*)vp;
    cudaGetSymbolAddress(&vp, g_Perm2); P2p = (int*)vp;

    const int LV_N[4]  = {4096, 3277, 2622, 2098};
    const int LV_LD[4] = {4096, 3328, 2688, 2176};
    float* Abuf[4] = {A0p, A1p, A2p, A3p};
    int* permB[3] = {P0p, P1p, P2p};
    const float* poolp[3] = {p1, p2, p3};
    const float* dW[3] = {W1, W2, W3};
    const float* db[3] = {b1, b2, b3};
    float* xsave[3] = {Xs0p, Xs1p, Xs2p};

    // build A0
    k_zero<<<(4096 * 4096 + 255) / 256, 256>>>(A0p, 4096 * 4096);
    k_edges<<<(NEDGE + 255) / 256, 256>>>(ei, A0p);
    k_eye<<<(4096 + 255) / 256, 256>>>(A0p);

    // first down conv
    run_gcn(A0p, 4096, 4096, x, 20, W0, b0, 64, true, Xs0p,
            XWp, Zp, Yp, Disp, Fillp, Partp);

    float* xcur = Xs0p;
    for (int i = 0; i < 3; i++) {
        int n = LV_N[i], ld = LV_LD[i];
        int kn = LV_N[i + 1], Mpad = LV_LD[i + 1];
        // pooling: score -> sort -> gather x
        k_score<<<(n + 63) / 64, 64>>>(xcur, poolp[i], Scorep, n);
        k_sort<<<1, 1024>>>(Scorep, n, kn, permB[i], Svalp);
        k_gatherx<<<(kn * 64 + 255) / 256, 256>>>(xcur, permB[i], Svalp, Xap, kn);
        // pooled augmented adjacency: A_next = M[perm,:] @ M[:,perm]
        int totR = Mpad * ld;
        k_gMr<<<(totR + 255) / 256, 256>>>(Abuf[i], permB[i], Mrp, kn, n, ld, ld, totR);
        int totC = ld * Mpad;
        k_gMc<<<(totC + 255) / 256, 256>>>(Abuf[i], permB[i], Mcp, kn, n, Mpad, ld, totC);
        dim3 gg(Mpad / 128, Mpad / 128);
        k_sgemm<<<gg, 256>>>(Mrp, Mcp, Abuf[i + 1], Mpad, Mpad, ld);
        k_zdiag<<<(kn + 255) / 256, 256>>>(Abuf[i + 1], Mpad, kn);
        // down conv at new level
        float* xout = (i < 2) ? xsave[i + 1] : Xbp;
        run_gcn(Abuf[i + 1], kn, Mpad, Xap, 64, dW[i], db[i], 64, true, xout,
                XWp, Zp, Yp, Disp, Fillp, Partp);
        xcur = xout;
    }

    // up path
    const float* dU[3] = {U0, U1, U2};
    const float* dc[3] = {c0, c1, c2};
    for (int i = 0; i < 3; i++) {
        int j = 2 - i;
        int nres = LV_N[j], ld = LV_LD[j];
        int kn = LV_N[j + 1];
        k_copy<<<(nres * 64 + 255) / 256, 256>>>(xsave[j], Xupp, nres * 64);
        k_scatadd<<<(kn * 64 + 255) / 256, 256>>>(xcur, permB[j], Xupp, kn);
        int cout = (i == 2) ? 20 : 64;
        bool dorelu = (i < 2);
        float* xo;
        if (i == 2)      xo = (float*)d_out;
        else if (i == 0) xo = Xap;
        else             xo = Xbp;
        run_gcn(Abuf[j], nres, ld, Xupp, 64, dU[i], dc[i], cout, dorelu, xo,
                XWp, Zp, Yp, Disp, Fillp, Partp);
        xcur = xo;
    }
}

// round 4
// speedup vs baseline: 2.1960x; 2.1960x over previous
#include <cuda_runtime.h>
#include <cuda_bf16.h>
#include <math.h>
#include <stdint.h>

typedef __nv_bfloat16 bf16;
#define NEDGE 131072

// Level sizes: n (real), ld (padded to mult of 128)
// L0: 4096/4096  L1: 3277/3328  L2: 2622/2688  L3: 2098/2176

__device__ float g_A0[4096*4096];
__device__ float g_A1[3328*3328];
__device__ float g_A2[2688*2688];
__device__ float g_A3[2176*2176];
__device__ float g_Mr[3328*4096];          // arena A: Mr hi(+lo) bf16
__device__ float g_Mc[3328*4096];          // arena B: McT hi(+lo) bf16
__device__ unsigned short g_Mt[4096u*4096u]; // M^T bf16 hi (and lo at L3, second half)
__device__ float g_Xs0[4096*64];
__device__ float g_Xs1[4096*64];
__device__ float g_Xs2[4096*64];
__device__ float g_Xa[4096*64];
__device__ float g_Xb[4096*64];
__device__ float g_Xup[4096*64];
__device__ float g_XW[4096*64];
__device__ float g_Z[4096*64];
__device__ float g_Y[4096*64];
__device__ float g_Part[32*4096];
__device__ float g_Dis[4096];
__device__ float g_Fill[4096];
__device__ float g_Score[4096];
__device__ float g_Sval[4096];
__device__ int   g_Perm0[4096];
__device__ int   g_Perm1[4096];
__device__ int   g_Perm2[4096];

// ---------------- helpers ----------------

__device__ __forceinline__ uint32_t smem_u32(const void* p) {
    uint32_t a;
    asm("{ .reg .u64 t; cvta.to.shared.u64 t, %1; cvt.u32.u64 %0, t; }" : "=r"(a) : "l"(p));
    return a;
}
__device__ __forceinline__ void cpa16(uint32_t s, const void* g) {
    asm volatile("cp.async.cg.shared.global [%0], [%1], 16;" :: "r"(s), "l"(g));
}
__device__ __forceinline__ void ldm4(uint32_t a, uint32_t& r0, uint32_t& r1,
                                     uint32_t& r2, uint32_t& r3) {
    asm volatile("ldmatrix.sync.aligned.m8n8.x4.shared.b16 {%0,%1,%2,%3}, [%4];"
                 : "=r"(r0), "=r"(r1), "=r"(r2), "=r"(r3) : "r"(a));
}
__device__ __forceinline__ void mma16816(float* d, const uint32_t* a, const uint32_t* b) {
    asm volatile(
        "mma.sync.aligned.m16n8k16.row.col.f32.bf16.bf16.f32 "
        "{%0,%1,%2,%3}, {%4,%5,%6,%7}, {%8,%9}, {%0,%1,%2,%3};"
        : "+f"(d[0]), "+f"(d[1]), "+f"(d[2]), "+f"(d[3])
        : "r"(a[0]), "r"(a[1]), "r"(a[2]), "r"(a[3]), "r"(b[0]), "r"(b[1]));
}

// ---------------- bf16 tensor-core GEMM ----------------
// C[M x M] = sum_passes A_p[M x K] @ B_p[M x K]^T  (both row-major bf16)
// passes: 0:(Ah,Bh) 1:(Ah,Bl) 2:(Al,Bh). M mult 128, K mult 64.
#define SMEM_GEMM 65536

__global__ void __launch_bounds__(256) k_mma(const bf16* __restrict__ Ah,
                                             const bf16* __restrict__ Al,
                                             const bf16* __restrict__ Bh,
                                             const bf16* __restrict__ Bl,
                                             float* __restrict__ C,
                                             int M, int K, int npass) {
    extern __shared__ char sm[];
    uint32_t sb = smem_u32(sm);
    int tid = threadIdx.x;
    int lane = tid & 31, wid = tid >> 5;
    int m0 = blockIdx.y * 128, n0 = blockIdx.x * 128;
    int wm = (wid & 1) * 64, wn = (wid >> 1) * 32;
    int KC = K >> 6;
    int TT = npass * KC;

    float acc[4][4][4];
#pragma unroll
    for (int i = 0; i < 4; i++)
#pragma unroll
        for (int j = 0; j < 4; j++)
#pragma unroll
            for (int v = 0; v < 4; v++) acc[i][j][v] = 0.f;

    auto issue = [&](int cc, int buf) {
        int pass = cc / KC, kt = cc - pass * KC;
        const bf16* Ap = (pass == 2) ? Al : Ah;
        const bf16* Bp = (pass == 1) ? Bl : Bh;
        const char* ag = (const char*)(Ap + (size_t)m0 * K + kt * 64);
        const char* bg = (const char*)(Bp + (size_t)n0 * K + kt * 64);
        uint32_t as = sb + buf * 16384;
        uint32_t bs = sb + 32768 + buf * 16384;
#pragma unroll
        for (int j = 0; j < 4; j++) {
            int q = tid + 256 * j;
            int r = q >> 3, cb = (q & 7) * 16;
            int bo = r * 128 + cb;
            int sw = bo ^ ((bo >> 3) & 0x70);
            cpa16(as + sw, ag + (size_t)r * (K * 2) + cb);
            cpa16(bs + sw, bg + (size_t)r * (K * 2) + cb);
        }
        asm volatile("cp.async.commit_group;");
    };

    issue(0, 0);
    for (int cc = 0; cc < TT; cc++) {
        int buf = cc & 1;
        if (cc + 1 < TT) {
            issue(cc + 1, buf ^ 1);
            asm volatile("cp.async.wait_group 1;");
        } else {
            asm volatile("cp.async.wait_group 0;");
        }
        __syncthreads();
        uint32_t asbuf = sb + buf * 16384;
        uint32_t bsbuf = sb + 32768 + buf * 16384;
#pragma unroll
        for (int ks = 0; ks < 4; ks++) {
            uint32_t a[4][4], b[4][2];
#pragma unroll
            for (int mi = 0; mi < 4; mi++) {
                int row = wm + mi * 16 + (lane & 7) + ((lane >> 3) & 1) * 8;
                int cbyt = ks * 32 + ((lane >> 4) & 1) * 16;
                int bo = row * 128 + cbyt;
                ldm4(asbuf + (bo ^ ((bo >> 3) & 0x70)),
                     a[mi][0], a[mi][1], a[mi][2], a[mi][3]);
            }
#pragma unroll
            for (int h = 0; h < 2; h++) {
                int row = wn + h * 16 + (lane & 7) + ((lane >> 4) & 1) * 8;
                int cbyt = ks * 32 + ((lane >> 3) & 1) * 16;
                int bo = row * 128 + cbyt;
                uint32_t r0, r1, r2, r3;
                ldm4(bsbuf + (bo ^ ((bo >> 3) & 0x70)), r0, r1, r2, r3);
                b[2 * h][0] = r0; b[2 * h][1] = r1;
                b[2 * h + 1][0] = r2; b[2 * h + 1][1] = r3;
            }
#pragma unroll
            for (int mi = 0; mi < 4; mi++)
#pragma unroll
                for (int ni = 0; ni < 4; ni++)
                    mma16816(acc[mi][ni], a[mi], b[ni]);
        }
        __syncthreads();
    }

    int g = lane >> 2, t = lane & 3;
#pragma unroll
    for (int mi = 0; mi < 4; mi++)
#pragma unroll
        for (int ni = 0; ni < 4; ni++) {
            int row = m0 + wm + mi * 16 + g;
            int col = n0 + wn + ni * 8 + 2 * t;
            float2 v0 = make_float2(acc[mi][ni][0], acc[mi][ni][1]);
            float2 v1 = make_float2(acc[mi][ni][2], acc[mi][ni][3]);
            *(float2*)&C[(size_t)row * M + col] = v0;
            *(float2*)&C[(size_t)(row + 8) * M + col] = v1;
        }
}

// ---------------- basic kernels ----------------

__global__ void k_zero(float* p, int n) {
    int i = blockIdx.x * blockDim.x + threadIdx.x;
    if (i < n) p[i] = 0.f;
}

__global__ void k_edges(const int* __restrict__ ei, float* __restrict__ A) {
    int e = blockIdx.x * blockDim.x + threadIdx.x;
    if (e < NEDGE) {
        int s = ei[e], d = ei[NEDGE + e];
        if (s != d) atomicAdd(&A[(size_t)s * 4096 + d], 1.f);
    }
}

__global__ void k_eye(float* A) {
    int i = blockIdx.x * blockDim.x + threadIdx.x;
    if (i < 4096) A[(size_t)i * 4096 + i] += 1.f;
}

__global__ void k_xw(const float* __restrict__ X, const float* __restrict__ W,
                     float* __restrict__ XW, int cin, int cout) {
    __shared__ float sx[64];
    int r = blockIdx.x;
    int f = threadIdx.x;
    for (int k = f; k < cin; k += 64) sx[k] = X[(size_t)r * cin + k];
    __syncthreads();
    float acc = 0.f;
    if (f < cout) {
        for (int k = 0; k < cin; k++) acc += sx[k] * W[k * cout + f];
    }
    XW[(size_t)r * 64 + f] = (f < cout) ? acc : 0.f;
}

__global__ void k_colsum(const float* __restrict__ A, float* __restrict__ part,
                         int n, int ld) {
    int c = blockIdx.x * blockDim.x + threadIdx.x;
    int ch = blockIdx.y;
    if (c >= ld) return;
    int rpc = (n + 31) >> 5;
    int r0 = ch * rpc, r1 = min(r0 + rpc, n);
    float s = 0.f;
    for (int r = r0; r < r1; r++) s += A[(size_t)r * ld + c];
    part[ch * 4096 + c] = s;
}

__global__ void k_dis(const float* __restrict__ A, const float* __restrict__ part,
                      float* __restrict__ dis, float* __restrict__ fill, int n, int ld) {
    int c = blockIdx.x * blockDim.x + threadIdx.x;
    if (c >= ld) return;
    if (c >= n) { dis[c] = 0.f; fill[c] = 0.f; return; }
    float s = 0.f;
#pragma unroll
    for (int ch = 0; ch < 32; ch++) s += part[ch * 4096 + c];
    float F = (A[(size_t)c * ld + c] == 0.f) ? 2.f : 0.f;
    float d = s + F;
    dis[c]  = (d > 0.f) ? (1.f / sqrtf(d)) : 0.f;
    fill[c] = F;
}

__global__ void k_scale(const float* __restrict__ XW, const float* __restrict__ dis,
                        float* __restrict__ Z, int n, int ld) {
    int idx = blockIdx.x * blockDim.x + threadIdx.x;
    if (idx >= ld * 64) return;
    int r = idx >> 6;
    Z[idx] = (r < n) ? dis[r] * XW[idx] : 0.f;
}

__global__ void __launch_bounds__(256) k_atz(const float* __restrict__ A,
                                             const float* __restrict__ Z,
                                             float* __restrict__ Y, int ld) {
    __shared__ float As[16][64];
    __shared__ float Zs[16][64];
    int mb = blockIdx.x * 64;
    int tid = threadIdx.x;
    int tm = (tid & 15) * 4;
    int tf = (tid >> 4) * 4;
    float acc[4][4] = {};
    for (int k0 = 0; k0 < ld; k0 += 16) {
        for (int idx = tid; idx < 16 * 64; idx += 256) {
            int kk = idx >> 6, mm = idx & 63;
            As[kk][mm] = A[(size_t)(k0 + kk) * ld + mb + mm];
            Zs[kk][mm] = Z[(size_t)(k0 + kk) * 64 + mm];
        }
        __syncthreads();
#pragma unroll
        for (int kk = 0; kk < 16; kk++) {
            float a[4], b[4];
#pragma unroll
            for (int i = 0; i < 4; i++) a[i] = As[kk][tm + i];
#pragma unroll
            for (int j = 0; j < 4; j++) b[j] = Zs[kk][tf + j];
#pragma unroll
            for (int i = 0; i < 4; i++)
#pragma unroll
                for (int j = 0; j < 4; j++) acc[i][j] += a[i] * b[j];
        }
        __syncthreads();
    }
#pragma unroll
    for (int i = 0; i < 4; i++)
#pragma unroll
        for (int j = 0; j < 4; j++)
            Y[(size_t)(mb + tm + i) * 64 + tf + j] = acc[i][j];
}

__global__ void k_fin(const float* __restrict__ Y, const float* __restrict__ Z,
                      const float* __restrict__ dis, const float* __restrict__ fill,
                      const float* __restrict__ bias, float* __restrict__ out,
                      int n, int cout, int dorelu) {
    int idx = blockIdx.x * blockDim.x + threadIdx.x;
    if (idx >= n * cout) return;
    int c = idx / cout, f = idx - c * cout;
    float v = dis[c] * (Y[(size_t)c * 64 + f] + fill[c] * Z[(size_t)c * 64 + f]) + bias[f];
    if (dorelu) v = fmaxf(v, 0.f);
    out[idx] = v;
}

__global__ void k_score(const float* __restrict__ X, const float* __restrict__ p,
                        float* __restrict__ score, int n) {
    int r = blockIdx.x * blockDim.x + threadIdx.x;
    if (r >= n) return;
    float dot = 0.f, pn = 0.f;
#pragma unroll
    for (int k = 0; k < 64; k++) { dot += X[(size_t)r * 64 + k] * p[k]; pn += p[k] * p[k]; }
    score[r] = tanhf(dot / sqrtf(pn));
}

__global__ void k_sort(const float* __restrict__ score, int n, int k,
                       int* __restrict__ perm, float* __restrict__ sval) {
    __shared__ float s[4096];
    __shared__ int id[4096];
    int tid = threadIdx.x;
    for (int i = tid; i < 4096; i += 1024) { s[i] = (i < n) ? score[i] : -INFINITY; id[i] = i; }
    __syncthreads();
    for (int sz = 2; sz <= 4096; sz <<= 1) {
        for (int j = sz >> 1; j > 0; j >>= 1) {
            for (int i = tid; i < 4096; i += 1024) {
                int ixj = i ^ j;
                if (ixj > i) {
                    float si = s[i], sj = s[ixj];
                    int ii = id[i], ij = id[ixj];
                    bool before = (si > sj) || (si == sj && ii < ij);
                    bool up = ((i & sz) == 0);
                    if (up ? !before : before) {
                        s[i] = sj; s[ixj] = si; id[i] = ij; id[ixj] = ii;
                    }
                }
            }
            __syncthreads();
        }
    }
    for (int a = tid; a < k; a += 1024) { perm[a] = id[a]; sval[a] = s[a]; }
}

__global__ void k_gatherx(const float* __restrict__ X, const int* __restrict__ perm,
                          const float* __restrict__ sval, float* __restrict__ Xo, int k) {
    int idx = blockIdx.x * blockDim.x + threadIdx.x;
    if (idx >= k * 64) return;
    int a = idx >> 6, f = idx & 63;
    Xo[idx] = X[(size_t)perm[a] * 64 + f] * sval[a];
}

// Mr[a,k] = M[perm[a],k] in bf16 (M = A with diag 1); optional lo residual.
__global__ void k_gMr(const float* __restrict__ A, const int* __restrict__ perm,
                      bf16* __restrict__ out, bf16* __restrict__ outLo,
                      int kreal, int nreal, int ldA, int total) {
    int idx = blockIdx.x * blockDim.x + threadIdx.x;
    if (idx >= total) return;
    int a = idx / ldA, k = idx - a * ldA;
    float v = 0.f;
    if (a < kreal && k < nreal) {
        int p = perm[a];
        v = (p == k) ? 1.f : A[(size_t)p * ldA + k];
    }
    bf16 h = __float2bfloat16(v);
    out[idx] = h;
    if (outLo) outLo[idx] = __float2bfloat16(v - __bfloat162float(h));
}

// Mt[c][r] = M[r][c] (diag 1, zero pads), bf16 hi (+lo). ld mult of 64.
__global__ void __launch_bounds__(256) k_trM(const float* __restrict__ A,
                                             bf16* __restrict__ MtH,
                                             bf16* __restrict__ MtL,
                                             int n, int ld) {
    __shared__ float t[64][65];
    int r0 = blockIdx.y * 64, c0 = blockIdx.x * 64;
    int tid = threadIdx.x;
    int c = tid & 63, r4 = tid >> 6;
#pragma unroll
    for (int p = 0; p < 16; p++) {
        int r = r4 + p * 4;
        int gr = r0 + r, gc = c0 + c;
        float v = 0.f;
        if (gr < n && gc < n) v = (gr == gc) ? 1.f : A[(size_t)gr * ld + gc];
        t[r][c] = v;
    }
    __syncthreads();
#pragma unroll
    for (int p = 0; p < 16; p++) {
        int cc = r4 + p * 4;
        float v = t[c][cc];
        size_t o = (size_t)(c0 + cc) * ld + r0 + c;
        bf16 h = __float2bfloat16(v);
        MtH[o] = h;
        if (MtL) MtL[o] = __float2bfloat16(v - __bfloat162float(h));
    }
}

// row-gather bf16: out[a][0:K] = (a<kreal) ? src[perm[a]][0:K] : 0 ; by 16B
__global__ void k_grow(const bf16* __restrict__ src, const int* __restrict__ perm,
                       bf16* __restrict__ out, int kreal, int K, int total8) {
    int idx = blockIdx.x * blockDim.x + threadIdx.x;
    if (idx >= total8) return;
    int K8 = K >> 3;
    int a = idx / K8, k8 = idx - a * K8;
    uint4 v = make_uint4(0, 0, 0, 0);
    if (a < kreal) v = *(const uint4*)(src + (size_t)perm[a] * K + k8 * 8);
    *(uint4*)(out + (size_t)a * K + k8 * 8) = v;
}

__global__ void k_zdiag(float* A, int ld, int k) {
    int a = blockIdx.x * blockDim.x + threadIdx.x;
    if (a < k) A[(size_t)a * ld + a] = 0.f;
}

__global__ void k_copy(const float* __restrict__ src, float* __restrict__ dst, int n) {
    int i = blockIdx.x * blockDim.x + threadIdx.x;
    if (i < n) dst[i] = src[i];
}

__global__ void k_scatadd(const float* __restrict__ Xc, const int* __restrict__ perm,
                          float* __restrict__ Xup, int k) {
    int idx = blockIdx.x * blockDim.x + threadIdx.x;
    if (idx >= k * 64) return;
    int a = idx >> 6, f = idx & 63;
    Xup[(size_t)perm[a] * 64 + f] += Xc[idx];
}

// ---------------- host orchestration ----------------

static void run_gcn(const float* A, int n, int ld, const float* X, int cin,
                    const float* W, const float* bias, int cout, bool dorelu,
                    float* Xout, float* pXW, float* pZ, float* pY,
                    float* pDis, float* pFill, float* pPart) {
    k_xw<<<n, 64>>>(X, W, pXW, cin, cout);
    dim3 g1((ld + 255) / 256, 32);
    k_colsum<<<g1, 256>>>(A, pPart, n, ld);
    k_dis<<<(ld + 255) / 256, 256>>>(A, pPart, pDis, pFill, n, ld);
    k_scale<<<(ld * 64 + 255) / 256, 256>>>(pXW, pDis, pZ, n, ld);
    k_atz<<<ld / 64, 256>>>(A, pZ, pY, ld);
    k_fin<<<(n * cout + 255) / 256, 256>>>(pY, pZ, pDis, pFill, bias, Xout, n, cout,
                                           dorelu ? 1 : 0);
}

extern "C" void kernel_launch(void* const* d_in, const int* in_sizes, int n_in,
                              void* d_out, int out_size) {
    const float* x  = (const float*)d_in[0];
    const int*   ei = (const int*)d_in[1];
    const float* W0 = (const float*)d_in[2];  const float* b0 = (const float*)d_in[3];
    const float* W1 = (const float*)d_in[4];  const float* b1 = (const float*)d_in[5];
    const float* W2 = (const float*)d_in[6];  const float* b2 = (const float*)d_in[7];
    const float* W3 = (const float*)d_in[8];  const float* b3 = (const float*)d_in[9];
    const float* p1 = (const float*)d_in[10];
    const float* p2 = (const float*)d_in[11];
    const float* p3 = (const float*)d_in[12];
    const float* U0 = (const float*)d_in[13]; const float* c0 = (const float*)d_in[14];
    const float* U1 = (const float*)d_in[15]; const float* c1 = (const float*)d_in[16];
    const float* U2 = (const float*)d_in[17]; const float* c2 = (const float*)d_in[18];

    cudaFuncSetAttribute(k_mma, cudaFuncAttributeMaxDynamicSharedMemorySize, SMEM_GEMM);

    void* vp;
    float *A0p, *A1p, *A2p, *A3p, *ArAf, *ArBf;
    unsigned short* Mtp;
    float *Xs0p, *Xs1p, *Xs2p, *Xap, *Xbp, *Xupp, *XWp, *Zp, *Yp, *Partp;
    float *Disp, *Fillp, *Scorep, *Svalp;
    int *P0p, *P1p, *P2p;
    cudaGetSymbolAddress(&vp, g_A0);  A0p  = (float*)vp;
    cudaGetSymbolAddress(&vp, g_A1);  A1p  = (float*)vp;
    cudaGetSymbolAddress(&vp, g_A2);  A2p  = (float*)vp;
    cudaGetSymbolAddress(&vp, g_A3);  A3p  = (float*)vp;
    cudaGetSymbolAddress(&vp, g_Mr);  ArAf = (float*)vp;
    cudaGetSymbolAddress(&vp, g_Mc);  ArBf = (float*)vp;
    cudaGetSymbolAddress(&vp, g_Mt);  Mtp  = (unsigned short*)vp;
    cudaGetSymbolAddress(&vp, g_Xs0); Xs0p = (float*)vp;
    cudaGetSymbolAddress(&vp, g_Xs1); Xs1p = (float*)vp;
    cudaGetSymbolAddress(&vp, g_Xs2); Xs2p = (float*)vp;
    cudaGetSymbolAddress(&vp, g_Xa);  Xap  = (float*)vp;
    cudaGetSymbolAddress(&vp, g_Xb);  Xbp  = (float*)vp;
    cudaGetSymbolAddress(&vp, g_Xup); Xupp = (float*)vp;
    cudaGetSymbolAddress(&vp, g_XW);  XWp  = (float*)vp;
    cudaGetSymbolAddress(&vp, g_Z);   Zp   = (float*)vp;
    cudaGetSymbolAddress(&vp, g_Y);   Yp   = (float*)vp;
    cudaGetSymbolAddress(&vp, g_Part); Partp = (float*)vp;
    cudaGetSymbolAddress(&vp, g_Dis);  Disp  = (float*)vp;
    cudaGetSymbolAddress(&vp, g_Fill); Fillp = (float*)vp;
    cudaGetSymbolAddress(&vp, g_Score); Scorep = (float*)vp;
    cudaGetSymbolAddress(&vp, g_Sval);  Svalp  = (float*)vp;
    cudaGetSymbolAddress(&vp, g_Perm0); P0p = (int*)vp;
    cudaGetSymbolAddress(&vp, g_Perm1); P1p = (int*)vp;
    cudaGetSymbolAddress(&vp, g_Perm2); P2p = (int*)vp;

    const int LV_N[4]  = {4096, 3277, 2622, 2098};
    const int LV_LD[4] = {4096, 3328, 2688, 2176};
    float* Abuf[4] = {A0p, A1p, A2p, A3p};
    int* permB[3] = {P0p, P1p, P2p};
    const float* poolp[3] = {p1, p2, p3};
    const float* dW[3] = {W1, W2, W3};
    const float* db[3] = {b1, b2, b3};
    float* xsave[3] = {Xs0p, Xs1p, Xs2p};

    // build A0
    k_zero<<<(4096 * 4096 + 255) / 256, 256>>>(A0p, 4096 * 4096);
    k_edges<<<(NEDGE + 255) / 256, 256>>>(ei, A0p);
    k_eye<<<(4096 + 255) / 256, 256>>>(A0p);

    // first down conv
    run_gcn(A0p, 4096, 4096, x, 20, W0, b0, 64, true, Xs0p,
            XWp, Zp, Yp, Disp, Fillp, Partp);

    float* xcur = Xs0p;
    for (int i = 0; i < 3; i++) {
        int n = LV_N[i], ld = LV_LD[i];
        int kn = LV_N[i + 1], Mpad = LV_LD[i + 1];
        // pooling: score -> sort -> gather x
        k_score<<<(n + 63) / 64, 64>>>(xcur, poolp[i], Scorep, n);
        k_sort<<<1, 1024>>>(Scorep, n, kn, permB[i], Svalp);
        k_gatherx<<<(kn * 64 + 255) / 256, 256>>>(xcur, permB[i], Svalp, Xap, kn);

        // pooled augmented adjacency: A_next = M[perm,:] @ M[:,perm]
        int sz = Mpad * ld;
        int split = (i == 2);
        bf16* MrH = (bf16*)ArAf;
        bf16* MrL = split ? MrH + (size_t)sz : nullptr;
        bf16* MtH = (bf16*)Mtp;
        bf16* MtL = split ? MtH + (size_t)ld * ld : nullptr;
        bf16* McTH = (bf16*)ArBf;
        bf16* McTL = split ? McTH + (size_t)sz : nullptr;

        k_gMr<<<(sz + 255) / 256, 256>>>(Abuf[i], permB[i], MrH, MrL, kn, n, ld, sz);
        dim3 gt(ld / 64, ld / 64);
        k_trM<<<gt, 256>>>(Abuf[i], MtH, MtL, n, ld);
        int tot8 = sz >> 3;
        k_grow<<<(tot8 + 255) / 256, 256>>>(MtH, permB[i], McTH, kn, ld, tot8);
        if (split) k_grow<<<(tot8 + 255) / 256, 256>>>(MtL, permB[i], McTL, kn, ld, tot8);

        dim3 gg(Mpad / 128, Mpad / 128);
        k_mma<<<gg, 256, SMEM_GEMM>>>(MrH, MrL, McTH, McTL, Abuf[i + 1], Mpad, ld,
                                      split ? 3 : 1);
        k_zdiag<<<(kn + 255) / 256, 256>>>(Abuf[i + 1], Mpad, kn);

        // down conv at new level
        float* xout = (i < 2) ? xsave[i + 1] : Xbp;
        run_gcn(Abuf[i + 1], kn, Mpad, Xap, 64, dW[i], db[i], 64, true, xout,
                XWp, Zp, Yp, Disp, Fillp, Partp);
        xcur = xout;
    }

    // up path
    const float* dU[3] = {U0, U1, U2};
    const float* dc[3] = {c0, c1, c2};
    for (int i = 0; i < 3; i++) {
        int j = 2 - i;
        int nres = LV_N[j], ld = LV_LD[j];
        int kn = LV_N[j + 1];
        k_copy<<<(nres * 64 + 255) / 256, 256>>>(xsave[j], Xupp, nres * 64);
        k_scatadd<<<(kn * 64 + 255) / 256, 256>>>(xcur, permB[j], Xupp, kn);
        int cout = (i == 2) ? 20 : 64;
        bool dorelu = (i < 2);
        float* xo;
        if (i == 2)      xo = (float*)d_out;
        else if (i == 0) xo = Xap;
        else             xo = Xbp;
        run_gcn(Abuf[j], nres, ld, Xupp, 64, dU[i], dc[i], cout, dorelu, xo,
                XWp, Zp, Yp, Disp, Fillp, Partp);
        xcur = xo;
    }
}

// round 5
// speedup vs baseline: 2.3064x; 1.0503x over previous
#include <cuda_runtime.h>
#include <cuda_bf16.h>
#include <math.h>
#include <stdint.h>

typedef __nv_bfloat16 bf16;
#define NEDGE 131072

// Level sizes: n (real), ld (padded to mult of 128)
// L0: 4096/4096  L1: 3277/3328  L2: 2622/2688  L3: 2098/2176

__device__ float g_A0[4096*4096];
__device__ float g_A1[3328*3328];
__device__ float g_A2[2688*2688];
__device__ float g_Mr[3328*4096];            // arena A: Mr (bf16 at L1/L2, fp32 at L3)
__device__ float g_Mc[3328*4096];            // arena B: McT (bf16 at L1/L2, fp32 at L3)
__device__ unsigned short g_Mt[4096u*4096u]; // M^T scratch (bf16 L1/L2, fp32 L3)
__device__ float g_T1[2688*64];
__device__ float g_U[4096];
__device__ float g_Deg[4096];
__device__ float g_Diag[4096];
__device__ float g_Xs0[4096*64];
__device__ float g_Xs1[4096*64];
__device__ float g_Xs2[4096*64];
__device__ float g_Xa[4096*64];
__device__ float g_Xb[4096*64];
__device__ float g_Xup[4096*64];
__device__ float g_XW[4096*64];
__device__ float g_Z[4096*64];
__device__ float g_Y[4096*64];
__device__ float g_Part[32*4096];
__device__ float g_Dis[4096];
__device__ float g_Fill[4096];
__device__ float g_Score[4096];
__device__ float g_Sval[4096];
__device__ int   g_Perm0[4096];
__device__ int   g_Perm1[4096];
__device__ int   g_Perm2[4096];

// ---------------- helpers ----------------

__device__ __forceinline__ uint32_t smem_u32(const void* p) {
    uint32_t a;
    asm("{ .reg .u64 t; cvta.to.shared.u64 t, %1; cvt.u32.u64 %0, t; }" : "=r"(a) : "l"(p));
    return a;
}
__device__ __forceinline__ void cpa16(uint32_t s, const void* g) {
    asm volatile("cp.async.cg.shared.global [%0], [%1], 16;" :: "r"(s), "l"(g));
}
__device__ __forceinline__ void ldm4(uint32_t a, uint32_t& r0, uint32_t& r1,
                                     uint32_t& r2, uint32_t& r3) {
    asm volatile("ldmatrix.sync.aligned.m8n8.x4.shared.b16 {%0,%1,%2,%3}, [%4];"
                 : "=r"(r0), "=r"(r1), "=r"(r2), "=r"(r3) : "r"(a));
}
__device__ __forceinline__ void mma16816(float* d, const uint32_t* a, const uint32_t* b) {
    asm volatile(
        "mma.sync.aligned.m16n8k16.row.col.f32.bf16.bf16.f32 "
        "{%0,%1,%2,%3}, {%4,%5,%6,%7}, {%8,%9}, {%0,%1,%2,%3};"
        : "+f"(d[0]), "+f"(d[1]), "+f"(d[2]), "+f"(d[3])
        : "r"(a[0]), "r"(a[1]), "r"(a[2]), "r"(a[3]), "r"(b[0]), "r"(b[1]));
}

// ---------------- bf16 tensor-core GEMM ----------------
// C[M x M] = A[M x K] @ B[M x K]^T  (both row-major bf16). M mult 128, K mult 64.
#define SMEM_GEMM 65536

__global__ void __launch_bounds__(256) k_mma(const bf16* __restrict__ A,
                                             const bf16* __restrict__ B,
                                             float* __restrict__ C,
                                             int M, int K) {
    extern __shared__ char sm[];
    uint32_t sb = smem_u32(sm);
    int tid = threadIdx.x;
    int lane = tid & 31, wid = tid >> 5;
    int m0 = blockIdx.y * 128, n0 = blockIdx.x * 128;
    int wm = (wid & 1) * 64, wn = (wid >> 1) * 32;
    int TT = K >> 6;

    float acc[4][4][4];
#pragma unroll
    for (int i = 0; i < 4; i++)
#pragma unroll
        for (int j = 0; j < 4; j++)
#pragma unroll
            for (int v = 0; v < 4; v++) acc[i][j][v] = 0.f;

    auto issue = [&](int kt, int buf) {
        const char* ag = (const char*)(A + (size_t)m0 * K + kt * 64);
        const char* bg = (const char*)(B + (size_t)n0 * K + kt * 64);
        uint32_t as = sb + buf * 16384;
        uint32_t bs = sb + 32768 + buf * 16384;
#pragma unroll
        for (int j = 0; j < 4; j++) {
            int q = tid + 256 * j;
            int r = q >> 3, cb = (q & 7) * 16;
            int bo = r * 128 + cb;
            int sw = bo ^ ((bo >> 3) & 0x70);
            cpa16(as + sw, ag + (size_t)r * (K * 2) + cb);
            cpa16(bs + sw, bg + (size_t)r * (K * 2) + cb);
        }
        asm volatile("cp.async.commit_group;");
    };

    issue(0, 0);
    for (int cc = 0; cc < TT; cc++) {
        int buf = cc & 1;
        if (cc + 1 < TT) {
            issue(cc + 1, buf ^ 1);
            asm volatile("cp.async.wait_group 1;");
        } else {
            asm volatile("cp.async.wait_group 0;");
        }
        __syncthreads();
        uint32_t asbuf = sb + buf * 16384;
        uint32_t bsbuf = sb + 32768 + buf * 16384;
#pragma unroll
        for (int ks = 0; ks < 4; ks++) {
            uint32_t a[4][4], b[4][2];
#pragma unroll
            for (int mi = 0; mi < 4; mi++) {
                int row = wm + mi * 16 + (lane & 7) + ((lane >> 3) & 1) * 8;
                int cbyt = ks * 32 + ((lane >> 4) & 1) * 16;
                int bo = row * 128 + cbyt;
                ldm4(asbuf + (bo ^ ((bo >> 3) & 0x70)),
                     a[mi][0], a[mi][1], a[mi][2], a[mi][3]);
            }
#pragma unroll
            for (int h = 0; h < 2; h++) {
                int row = wn + h * 16 + (lane & 7) + ((lane >> 4) & 1) * 8;
                int cbyt = ks * 32 + ((lane >> 3) & 1) * 16;
                int bo = row * 128 + cbyt;
                uint32_t r0, r1, r2, r3;
                ldm4(bsbuf + (bo ^ ((bo >> 3) & 0x70)), r0, r1, r2, r3);
                b[2 * h][0] = r0; b[2 * h][1] = r1;
                b[2 * h + 1][0] = r2; b[2 * h + 1][1] = r3;
            }
#pragma unroll
            for (int mi = 0; mi < 4; mi++)
#pragma unroll
                for (int ni = 0; ni < 4; ni++)
                    mma16816(acc[mi][ni], a[mi], b[ni]);
        }
        __syncthreads();
    }

    int g = lane >> 2, t = lane & 3;
#pragma unroll
    for (int mi = 0; mi < 4; mi++)
#pragma unroll
        for (int ni = 0; ni < 4; ni++) {
            int row = m0 + wm + mi * 16 + g;
            int col = n0 + wn + ni * 8 + 2 * t;
            float2 v0 = make_float2(acc[mi][ni][0], acc[mi][ni][1]);
            float2 v1 = make_float2(acc[mi][ni][2], acc[mi][ni][3]);
            *(float2*)&C[(size_t)row * M + col] = v0;
            *(float2*)&C[(size_t)(row + 8) * M + col] = v1;
        }
}

// ---------------- basic kernels ----------------

__global__ void k_zero(float* p, int n) {
    int i = blockIdx.x * blockDim.x + threadIdx.x;
    if (i < n) p[i] = 0.f;
}

__global__ void k_edges(const int* __restrict__ ei, float* __restrict__ A) {
    int e = blockIdx.x * blockDim.x + threadIdx.x;
    if (e < NEDGE) {
        int s = ei[e], d = ei[NEDGE + e];
        if (s != d) atomicAdd(&A[(size_t)s * 4096 + d], 1.f);
    }
}

__global__ void k_eye(float* A) {
    int i = blockIdx.x * blockDim.x + threadIdx.x;
    if (i < 4096) A[(size_t)i * 4096 + i] += 1.f;
}

__global__ void k_xw(const float* __restrict__ X, const float* __restrict__ W,
                     float* __restrict__ XW, int cin, int cout) {
    __shared__ float sx[64];
    int r = blockIdx.x;
    int f = threadIdx.x;
    for (int k = f; k < cin; k += 64) sx[k] = X[(size_t)r * cin + k];
    __syncthreads();
    float acc = 0.f;
    if (f < cout) {
        for (int k = 0; k < cin; k++) acc += sx[k] * W[k * cout + f];
    }
    XW[(size_t)r * 64 + f] = (f < cout) ? acc : 0.f;
}

__global__ void k_colsum(const float* __restrict__ A, float* __restrict__ part,
                         int n, int ld) {
    int c = blockIdx.x * blockDim.x + threadIdx.x;
    int ch = blockIdx.y;
    if (c >= ld) return;
    int rpc = (n + 31) >> 5;
    int r0 = ch * rpc, r1 = min(r0 + rpc, n);
    float s = 0.f;
    for (int r = r0; r < r1; r++) s += A[(size_t)r * ld + c];
    part[ch * 4096 + c] = s;
}

__global__ void k_dis(const float* __restrict__ A, const float* __restrict__ part,
                      float* __restrict__ dis, float* __restrict__ fill, int n, int ld) {
    int c = blockIdx.x * blockDim.x + threadIdx.x;
    if (c >= ld) return;
    if (c >= n) { dis[c] = 0.f; fill[c] = 0.f; return; }
    float s = 0.f;
#pragma unroll
    for (int ch = 0; ch < 32; ch++) s += part[ch * 4096 + c];
    float F = (A[(size_t)c * ld + c] == 0.f) ? 2.f : 0.f;
    float d = s + F;
    dis[c]  = (d > 0.f) ? (1.f / sqrtf(d)) : 0.f;
    fill[c] = F;
}

__global__ void k_comb32(const float* __restrict__ part, float* __restrict__ u, int K) {
    int c = blockIdx.x * blockDim.x + threadIdx.x;
    if (c >= K) return;
    float s = 0.f;
#pragma unroll
    for (int ch = 0; ch < 32; ch++) s += part[ch * 4096 + c];
    u[c] = s;
}

// out[r] = sum_k P[r,k]*u[k], warp per row
__global__ void k_matvec(const float* __restrict__ P, const float* __restrict__ u,
                         float* __restrict__ out, int rows, int K) {
    int w = (blockIdx.x * blockDim.x + threadIdx.x) >> 5;
    int lane = threadIdx.x & 31;
    if (w >= rows) return;
    const float* p = P + (size_t)w * K;
    float s = 0.f;
    for (int k = lane; k < K; k += 32) s += p[k] * u[k];
#pragma unroll
    for (int o = 16; o; o >>= 1) s += __shfl_xor_sync(~0u, s, o);
    if (!lane) out[w] = s;
}

// out[r] = sum_k P[r,k]*Q[r,k], warp per row
__global__ void k_dotrows(const float* __restrict__ P, const float* __restrict__ Q,
                          float* __restrict__ out, int rows, int K) {
    int w = (blockIdx.x * blockDim.x + threadIdx.x) >> 5;
    int lane = threadIdx.x & 31;
    if (w >= rows) return;
    const float* p = P + (size_t)w * K;
    const float* q = Q + (size_t)w * K;
    float s = 0.f;
    for (int k = lane; k < K; k += 32) s += p[k] * q[k];
#pragma unroll
    for (int o = 16; o; o >>= 1) s += __shfl_xor_sync(~0u, s, o);
    if (!lane) out[w] = s;
}

__global__ void k_dis3(const float* __restrict__ deg, const float* __restrict__ diag3,
                       float* __restrict__ dis, int n, int ldp) {
    int c = blockIdx.x * blockDim.x + threadIdx.x;
    if (c >= ldp) return;
    if (c >= n) { dis[c] = 0.f; return; }
    float d = deg[c] - diag3[c] + 2.f;
    dis[c] = (d > 0.f) ? (1.f / sqrtf(d)) : 0.f;
}

__global__ void k_scale(const float* __restrict__ XW, const float* __restrict__ dis,
                        float* __restrict__ Z, int n, int ld) {
    int idx = blockIdx.x * blockDim.x + threadIdx.x;
    if (idx >= ld * 64) return;
    int r = idx >> 6;
    Z[idx] = (r < n) ? dis[r] * XW[idx] : 0.f;
}

// Y[ldA x 64] = A^T @ Z, A[nred x ldA] row-major, Z[nred x 64]. nred mult 16, ldA mult 64.
__global__ void __launch_bounds__(256) k_atzr(const float* __restrict__ A,
                                              const float* __restrict__ Z,
                                              float* __restrict__ Y,
                                              int nred, int ldA) {
    __shared__ float As[16][64];
    __shared__ float Zs[16][64];
    int mb = blockIdx.x * 64;
    int tid = threadIdx.x;
    int tm = (tid & 15) * 4;
    int tf = (tid >> 4) * 4;
    float acc[4][4] = {};
    for (int k0 = 0; k0 < nred; k0 += 16) {
        for (int idx = tid; idx < 16 * 64; idx += 256) {
            int kk = idx >> 6, mm = idx & 63;
            As[kk][mm] = A[(size_t)(k0 + kk) * ldA + mb + mm];
            Zs[kk][mm] = Z[(size_t)(k0 + kk) * 64 + mm];
        }
        __syncthreads();
#pragma unroll
        for (int kk = 0; kk < 16; kk++) {
            float a[4], b[4];
#pragma unroll
            for (int i = 0; i < 4; i++) a[i] = As[kk][tm + i];
#pragma unroll
            for (int j = 0; j < 4; j++) b[j] = Zs[kk][tf + j];
#pragma unroll
            for (int i = 0; i < 4; i++)
#pragma unroll
                for (int j = 0; j < 4; j++) acc[i][j] += a[i] * b[j];
        }
        __syncthreads();
    }
#pragma unroll
    for (int i = 0; i < 4; i++)
#pragma unroll
        for (int j = 0; j < 4; j++)
            Y[(size_t)(mb + tm + i) * 64 + tf + j] = acc[i][j];
}

// Y[r,0:64] = sum_k A[r,k]*T[k,0:64]; warp per row, K mult 128
__global__ void __launch_bounds__(256) k_rowmm(const float* __restrict__ A,
                                               const float* __restrict__ T,
                                               float* __restrict__ Y,
                                               int rows, int K) {
    __shared__ float Ts[128][64];
    int lane = threadIdx.x & 31, wl = threadIdx.x >> 5;
    int r = blockIdx.x * 8 + wl;
    float y0 = 0.f, y1 = 0.f;
    for (int k0 = 0; k0 < K; k0 += 128) {
        __syncthreads();
        for (int idx = threadIdx.x; idx < 128 * 64; idx += 256) {
            int kk = idx >> 6, f = idx & 63;
            Ts[kk][f] = T[(size_t)(k0 + kk) * 64 + f];
        }
        __syncthreads();
        if (r < rows) {
#pragma unroll
            for (int kb = 0; kb < 4; kb++) {
                float av = A[(size_t)r * K + k0 + kb * 32 + lane];
#pragma unroll
                for (int l = 0; l < 32; l++) {
                    float a = __shfl_sync(~0u, av, l);
                    y0 += a * Ts[kb * 32 + l][lane];
                    y1 += a * Ts[kb * 32 + l][lane + 32];
                }
            }
        }
    }
    if (r < rows) {
        Y[(size_t)r * 64 + lane] = y0;
        Y[(size_t)r * 64 + lane + 32] = y1;
    }
}

__global__ void k_fin(const float* __restrict__ Y, const float* __restrict__ Z,
                      const float* __restrict__ dis, const float* __restrict__ fill,
                      const float* __restrict__ bias, float* __restrict__ out,
                      int n, int cout, int dorelu) {
    int idx = blockIdx.x * blockDim.x + threadIdx.x;
    if (idx >= n * cout) return;
    int c = idx / cout, f = idx - c * cout;
    float v = dis[c] * (Y[(size_t)c * 64 + f] + fill[c] * Z[(size_t)c * 64 + f]) + bias[f];
    if (dorelu) v = fmaxf(v, 0.f);
    out[idx] = v;
}

__global__ void k_fin3(const float* __restrict__ Y, const float* __restrict__ Z,
                       const float* __restrict__ dis, const float* __restrict__ diag3,
                       const float* __restrict__ bias, float* __restrict__ out, int n) {
    int idx = blockIdx.x * blockDim.x + threadIdx.x;
    if (idx >= n * 64) return;
    int c = idx >> 6, f = idx & 63;
    float v = dis[c] * (Y[idx] - diag3[c] * Z[idx] + 2.f * Z[idx]) + bias[f];
    out[idx] = fmaxf(v, 0.f);
}

__global__ void k_score(const float* __restrict__ X, const float* __restrict__ p,
                        float* __restrict__ score, int n) {
    int r = blockIdx.x * blockDim.x + threadIdx.x;
    if (r >= n) return;
    float dot = 0.f, pn = 0.f;
#pragma unroll
    for (int k = 0; k < 64; k++) { dot += X[(size_t)r * 64 + k] * p[k]; pn += p[k] * p[k]; }
    score[r] = tanhf(dot / sqrtf(pn));
}

__global__ void k_sort(const float* __restrict__ score, int n, int k,
                       int* __restrict__ perm, float* __restrict__ sval) {
    __shared__ float s[4096];
    __shared__ int id[4096];
    int tid = threadIdx.x;
    for (int i = tid; i < 4096; i += 1024) { s[i] = (i < n) ? score[i] : -INFINITY; id[i] = i; }
    __syncthreads();
    for (int sz = 2; sz <= 4096; sz <<= 1) {
        for (int j = sz >> 1; j > 0; j >>= 1) {
            for (int i = tid; i < 4096; i += 1024) {
                int ixj = i ^ j;
                if (ixj > i) {
                    float si = s[i], sj = s[ixj];
                    int ii = id[i], ij = id[ixj];
                    bool before = (si > sj) || (si == sj && ii < ij);
                    bool up = ((i & sz) == 0);
                    if (up ? !before : before) {
                        s[i] = sj; s[ixj] = si; id[i] = ij; id[ixj] = ii;
                    }
                }
            }
            __syncthreads();
        }
    }
    for (int a = tid; a < k; a += 1024) { perm[a] = id[a]; sval[a] = s[a]; }
}

__global__ void k_gatherx(const float* __restrict__ X, const int* __restrict__ perm,
                          const float* __restrict__ sval, float* __restrict__ Xo, int k) {
    int idx = blockIdx.x * blockDim.x + threadIdx.x;
    if (idx >= k * 64) return;
    int a = idx >> 6, f = idx & 63;
    Xo[idx] = X[(size_t)perm[a] * 64 + f] * sval[a];
}

// Mr[a,k] = M[perm[a],k] in bf16 (M = A with diag 1)
__global__ void k_gMr(const float* __restrict__ A, const int* __restrict__ perm,
                      bf16* __restrict__ out, int kreal, int nreal, int ldA, int total) {
    int idx = blockIdx.x * blockDim.x + threadIdx.x;
    if (idx >= total) return;
    int a = idx / ldA, k = idx - a * ldA;
    float v = 0.f;
    if (a < kreal && k < nreal) {
        int p = perm[a];
        v = (p == k) ? 1.f : A[(size_t)p * ldA + k];
    }
    out[idx] = __float2bfloat16(v);
}

// fp32 variant
__global__ void k_gMrf(const float* __restrict__ A, const int* __restrict__ perm,
                       float* __restrict__ out, int kreal, int nreal, int ldA, int total) {
    int idx = blockIdx.x * blockDim.x + threadIdx.x;
    if (idx >= total) return;
    int a = idx / ldA, k = idx - a * ldA;
    float v = 0.f;
    if (a < kreal && k < nreal) {
        int p = perm[a];
        v = (p == k) ? 1.f : A[(size_t)p * ldA + k];
    }
    out[idx] = v;
}

// Mt[c][r] = M[r][c] (diag 1, zero pads), bf16. ld mult of 64.
__global__ void __launch_bounds__(256) k_trM(const float* __restrict__ A,
                                             bf16* __restrict__ Mt, int n, int ld) {
    __shared__ float t[64][65];
    int r0 = blockIdx.y * 64, c0 = blockIdx.x * 64;
    int tid = threadIdx.x;
    int c = tid & 63, r4 = tid >> 6;
#pragma unroll
    for (int p = 0; p < 16; p++) {
        int r = r4 + p * 4;
        int gr = r0 + r, gc = c0 + c;
        float v = 0.f;
        if (gr < n && gc < n) v = (gr == gc) ? 1.f : A[(size_t)gr * ld + gc];
        t[r][c] = v;
    }
    __syncthreads();
#pragma unroll
    for (int p = 0; p < 16; p++) {
        int cc = r4 + p * 4;
        Mt[(size_t)(c0 + cc) * ld + r0 + c] = __float2bfloat16(t[c][cc]);
    }
}

// fp32 transpose variant
__global__ void __launch_bounds__(256) k_trMf(const float* __restrict__ A,
                                              float* __restrict__ Mt, int n, int ld) {
    __shared__ float t[64][65];
    int r0 = blockIdx.y * 64, c0 = blockIdx.x * 64;
    int tid = threadIdx.x;
    int c = tid & 63, r4 = tid >> 6;
#pragma unroll
    for (int p = 0; p < 16; p++) {
        int r = r4 + p * 4;
        int gr = r0 + r, gc = c0 + c;
        float v = 0.f;
        if (gr < n && gc < n) v = (gr == gc) ? 1.f : A[(size_t)gr * ld + gc];
        t[r][c] = v;
    }
    __syncthreads();
#pragma unroll
    for (int p = 0; p < 16; p++) {
        int cc = r4 + p * 4;
        Mt[(size_t)(c0 + cc) * ld + r0 + c] = t[c][cc];
    }
}

// row-gather bf16: out[a][0:K] = (a<kreal) ? src[perm[a]][0:K] : 0 ; by 16B
__global__ void k_grow(const bf16* __restrict__ src, const int* __restrict__ perm,
                       bf16* __restrict__ out, int kreal, int K, int total8) {
    int idx = blockIdx.x * blockDim.x + threadIdx.x;
    if (idx >= total8) return;
    int K8 = K >> 3;
    int a = idx / K8, k8 = idx - a * K8;
    uint4 v = make_uint4(0, 0, 0, 0);
    if (a < kreal) v = *(const uint4*)(src + (size_t)perm[a] * K + k8 * 8);
    *(uint4*)(out + (size_t)a * K + k8 * 8) = v;
}

// row-gather fp32 by 16B
__global__ void k_growf(const float* __restrict__ src, const int* __restrict__ perm,
                        float* __restrict__ out, int kreal, int K, int total4) {
    int idx = blockIdx.x * blockDim.x + threadIdx.x;
    if (idx >= total4) return;
    int K4 = K >> 2;
    int a = idx / K4, k4 = idx - a * K4;
    float4 v = make_float4(0.f, 0.f, 0.f, 0.f);
    if (a < kreal) v = *(const float4*)(src + (size_t)perm[a] * K + k4 * 4);
    *(float4*)(out + (size_t)a * K + k4 * 4) = v;
}

__global__ void k_zdiag(float* A, int ld, int k) {
    int a = blockIdx.x * blockDim.x + threadIdx.x;
    if (a < k) A[(size_t)a * ld + a] = 0.f;
}

__global__ void k_copy(const float* __restrict__ src, float* __restrict__ dst, int n) {
    int i = blockIdx.x * blockDim.x + threadIdx.x;
    if (i < n) dst[i] = src[i];
}

__global__ void k_scatadd(const float* __restrict__ Xc, const int* __restrict__ perm,
                          float* __restrict__ Xup, int k) {
    int idx = blockIdx.x * blockDim.x + threadIdx.x;
    if (idx >= k * 64) return;
    int a = idx >> 6, f = idx & 63;
    Xup[(size_t)perm[a] * 64 + f] += Xc[idx];
}

// ---------------- host orchestration ----------------

static void run_gcn(const float* A, int n, int ld, const float* X, int cin,
                    const float* W, const float* bias, int cout, bool dorelu,
                    float* Xout, float* pXW, float* pZ, float* pY,
                    float* pDis, float* pFill, float* pPart) {
    k_xw<<<n, 64>>>(X, W, pXW, cin, cout);
    dim3 g1((ld + 255) / 256, 32);
    k_colsum<<<g1, 256>>>(A, pPart, n, ld);
    k_dis<<<(ld + 255) / 256, 256>>>(A, pPart, pDis, pFill, n, ld);
    k_scale<<<(ld * 64 + 255) / 256, 256>>>(pXW, pDis, pZ, n, ld);
    k_atzr<<<ld / 64, 256>>>(A, pZ, pY, ld, ld);
    k_fin<<<(n * cout + 255) / 256, 256>>>(pY, pZ, pDis, pFill, bias, Xout, n, cout,
                                           dorelu ? 1 : 0);
}

extern "C" void kernel_launch(void* const* d_in, const int* in_sizes, int n_in,
                              void* d_out, int out_size) {
    const float* x  = (const float*)d_in[0];
    const int*   ei = (const int*)d_in[1];
    const float* W0 = (const float*)d_in[2];  const float* b0 = (const float*)d_in[3];
    const float* W1 = (const float*)d_in[4];  const float* b1 = (const float*)d_in[5];
    const float* W2 = (const float*)d_in[6];  const float* b2 = (const float*)d_in[7];
    const float* W3 = (const float*)d_in[8];  const float* b3 = (const float*)d_in[9];
    const float* p1 = (const float*)d_in[10];
    const float* p2 = (const float*)d_in[11];
    const float* p3 = (const float*)d_in[12];
    const float* U0 = (const float*)d_in[13]; const float* c0 = (const float*)d_in[14];
    const float* U1 = (const float*)d_in[15]; const float* c1 = (const float*)d_in[16];
    const float* U2 = (const float*)d_in[17]; const float* c2 = (const float*)d_in[18];

    cudaFuncSetAttribute(k_mma, cudaFuncAttributeMaxDynamicSharedMemorySize, SMEM_GEMM);

    void* vp;
    float *A0p, *A1p, *A2p, *ArAf, *ArBf, *T1p, *Up, *Degp, *Diagp;
    unsigned short* Mtp;
    float *Xs0p, *Xs1p, *Xs2p, *Xap, *Xbp, *Xupp, *XWp, *Zp, *Yp, *Partp;
    float *Disp, *Fillp, *Scorep, *Svalp;
    int *P0p, *P1p, *P2p;
    cudaGetSymbolAddress(&vp, g_A0);  A0p  = (float*)vp;
    cudaGetSymbolAddress(&vp, g_A1);  A1p  = (float*)vp;
    cudaGetSymbolAddress(&vp, g_A2);  A2p  = (float*)vp;
    cudaGetSymbolAddress(&vp, g_Mr);  ArAf = (float*)vp;
    cudaGetSymbolAddress(&vp, g_Mc);  ArBf = (float*)vp;
    cudaGetSymbolAddress(&vp, g_Mt);  Mtp  = (unsigned short*)vp;
    cudaGetSymbolAddress(&vp, g_T1);  T1p  = (float*)vp;
    cudaGetSymbolAddress(&vp, g_U);   Up   = (float*)vp;
    cudaGetSymbolAddress(&vp, g_Deg); Degp = (float*)vp;
    cudaGetSymbolAddress(&vp, g_Diag); Diagp = (float*)vp;
    cudaGetSymbolAddress(&vp, g_Xs0); Xs0p = (float*)vp;
    cudaGetSymbolAddress(&vp, g_Xs1); Xs1p = (float*)vp;
    cudaGetSymbolAddress(&vp, g_Xs2); Xs2p = (float*)vp;
    cudaGetSymbolAddress(&vp, g_Xa);  Xap  = (float*)vp;
    cudaGetSymbolAddress(&vp, g_Xb);  Xbp  = (float*)vp;
    cudaGetSymbolAddress(&vp, g_Xup); Xupp = (float*)vp;
    cudaGetSymbolAddress(&vp, g_XW);  XWp  = (float*)vp;
    cudaGetSymbolAddress(&vp, g_Z);   Zp   = (float*)vp;
    cudaGetSymbolAddress(&vp, g_Y);   Yp   = (float*)vp;
    cudaGetSymbolAddress(&vp, g_Part); Partp = (float*)vp;
    cudaGetSymbolAddress(&vp, g_Dis);  Disp  = (float*)vp;
    cudaGetSymbolAddress(&vp, g_Fill); Fillp = (float*)vp;
    cudaGetSymbolAddress(&vp, g_Score); Scorep = (float*)vp;
    cudaGetSymbolAddress(&vp, g_Sval);  Svalp  = (float*)vp;
    cudaGetSymbolAddress(&vp, g_Perm0); P0p = (int*)vp;
    cudaGetSymbolAddress(&vp, g_Perm1); P1p = (int*)vp;
    cudaGetSymbolAddress(&vp, g_Perm2); P2p = (int*)vp;

    const int LV_N[4]  = {4096, 3277, 2622, 2098};
    const int LV_LD[4] = {4096, 3328, 2688, 2176};
    float* Abuf[3] = {A0p, A1p, A2p};
    int* permB[3] = {P0p, P1p, P2p};
    const float* poolp[3] = {p1, p2, p3};
    float* xsave[3] = {Xs0p, Xs1p, Xs2p};

    // build A0
    k_zero<<<(4096 * 4096 + 255) / 256, 256>>>(A0p, 4096 * 4096);
    k_edges<<<(NEDGE + 255) / 256, 256>>>(ei, A0p);
    k_eye<<<(4096 + 255) / 256, 256>>>(A0p);

    // first down conv
    run_gcn(A0p, 4096, 4096, x, 20, W0, b0, 64, true, Xs0p,
            XWp, Zp, Yp, Disp, Fillp, Partp);

    float* xcur = Xs0p;

    // down levels 1,2: materialize pooled augmented adjacency via bf16 HMMA
    const float* dW12[2] = {W1, W2};
    const float* db12[2] = {b1, b2};
    for (int i = 0; i < 2; i++) {
        int n = LV_N[i], ld = LV_LD[i];
        int kn = LV_N[i + 1], Mpad = LV_LD[i + 1];
        k_score<<<(n + 63) / 64, 64>>>(xcur, poolp[i], Scorep, n);
        k_sort<<<1, 1024>>>(Scorep, n, kn, permB[i], Svalp);
        k_gatherx<<<(kn * 64 + 255) / 256, 256>>>(xcur, permB[i], Svalp, Xap, kn);

        int sz = Mpad * ld;
        bf16* MrH = (bf16*)ArAf;
        bf16* MtH = (bf16*)Mtp;
        bf16* McTH = (bf16*)ArBf;
        k_gMr<<<(sz + 255) / 256, 256>>>(Abuf[i], permB[i], MrH, kn, n, ld, sz);
        dim3 gt(ld / 64, ld / 64);
        k_trM<<<gt, 256>>>(Abuf[i], MtH, n, ld);
        int tot8 = sz >> 3;
        k_grow<<<(tot8 + 255) / 256, 256>>>(MtH, permB[i], McTH, kn, ld, tot8);

        dim3 gg(Mpad / 128, Mpad / 128);
        k_mma<<<gg, 256, SMEM_GEMM>>>(MrH, McTH, Abuf[i + 1], Mpad, ld);
        k_zdiag<<<(kn + 255) / 256, 256>>>(Abuf[i + 1], Mpad, kn);

        float* xout = xsave[i + 1];
        run_gcn(Abuf[i + 1], kn, Mpad, Xap, 64, dW12[i], db12[i], 64, true, xout,
                XWp, Zp, Yp, Disp, Fillp, Partp);
        xcur = xout;
    }

    // down level 3: factored conv, never materialize A3
    {
        int n = LV_N[2], ld = LV_LD[2];          // 2622 / 2688
        int kn = LV_N[3], Mpad = LV_LD[3];       // 2098 / 2176
        k_score<<<(n + 63) / 64, 64>>>(xcur, poolp[2], Scorep, n);
        k_sort<<<1, 1024>>>(Scorep, n, kn, permB[2], Svalp);
        k_gatherx<<<(kn * 64 + 255) / 256, 256>>>(xcur, permB[2], Svalp, Xap, kn);

        int sz = Mpad * ld;
        float* Mrf  = ArAf;            // [Mpad x ld] fp32
        float* Mtf  = (float*)Mtp;     // [ld x ld] fp32
        float* McTf = ArBf;            // [Mpad x ld] fp32
        k_gMrf<<<(sz + 255) / 256, 256>>>(A2p, permB[2], Mrf, kn, n, ld, sz);
        dim3 gt(ld / 64, ld / 64);
        k_trMf<<<gt, 256>>>(A2p, Mtf, n, ld);
        int tot4 = sz >> 2;
        k_growf<<<(tot4 + 255) / 256, 256>>>(Mtf, permB[2], McTf, kn, ld, tot4);

        // XW, degrees, diag, dis
        k_xw<<<kn, 64>>>(Xap, W3, XWp, 64, 64);
        dim3 g1((ld + 255) / 256, 32);
        k_colsum<<<g1, 256>>>(Mrf, Partp, Mpad, ld);               // u partials over rows of Mr
        k_comb32<<<(ld + 255) / 256, 256>>>(Partp, Up, ld);
        k_matvec<<<(Mpad * 32 + 255) / 256, 256>>>(McTf, Up, Degp, Mpad, ld);
        k_dotrows<<<(Mpad * 32 + 255) / 256, 256>>>(Mrf, McTf, Diagp, Mpad, ld);
        k_dis3<<<(Mpad + 255) / 256, 256>>>(Degp, Diagp, Disp, kn, Mpad);
        k_scale<<<(Mpad * 64 + 255) / 256, 256>>>(XWp, Disp, Zp, kn, Mpad);

        // A3^T Z = McT * (Mr^T Z), then remove diag and add fill in epilogue
        k_atzr<<<ld / 64, 256>>>(Mrf, Zp, T1p, Mpad, ld);
        k_rowmm<<<Mpad / 8, 256>>>(McTf, T1p, Yp, Mpad, ld);
        k_fin3<<<(kn * 64 + 255) / 256, 256>>>(Yp, Zp, Disp, Diagp, b3, Xbp, kn);
        xcur = Xbp;
    }

    // up path (uses A2, A1, A0 — all materialized)
    const float* dU[3] = {U0, U1, U2};
    const float* dc[3] = {c0, c1, c2};
    for (int i = 0; i < 3; i++) {
        int j = 2 - i;
        int nres = LV_N[j], ld = LV_LD[j];
        int kn = LV_N[j + 1];
        k_copy<<<(nres * 64 + 255) / 256, 256>>>(xsave[j], Xupp, nres * 64);
        k_scatadd<<<(kn * 64 + 255) / 256, 256>>>(xcur, permB[j], Xupp, kn);
        int cout = (i == 2) ? 20 : 64;
        bool dorelu = (i < 2);
        float* xo;
        if (i == 2)      xo = (float*)d_out;
        else if (i == 0) xo = Xap;
        else             xo = Xbp;
        run_gcn(Abuf[j], nres, ld, Xupp, 64, dU[i], dc[i], cout, dorelu, xo,
                XWp, Zp, Yp, Disp, Fillp, Partp);
        xcur = xo;
    }
}